// round 14
// baseline (speedup 1.0000x reference)
#include <cuda_runtime.h>
#include <cuda_fp16.h>
#include <cstdint>

#define BATCH 32
#define T 4096
#define IN_DIM 256
#define MEM 256
#define HID 512
#define S 128
#define NB 32
#define USTRIDE (T + S)
#define HPAIR (T / 2)               // 2048 pairs per H row
#define MPAIR (MEM / 2)             // 128
#define XPAIR (IN_DIM / 2)          // 128
#define WPAIR ((MEM + IN_DIM) / 2)  // 256

#define UX_BLOCKS (BATCH * T / 16)                  // 8192 CTAs (2 rows/warp)
#define HTOT ((size_t)MEM * HPAIR)                  // 524288
#define WTOT ((size_t)HID * WPAIR)                  // 131072
#define NFLAG (BATCH * NB)                          // 1024
#define PREP_BLOCKS ((int)((HTOT + WTOT + NFLAG + 255) / 256))  // 2564

#define CONV_CTAS 2048
#define G2_CTAS   4096

// ---------------- scratch (device globals, 16B aligned for cp.async) --------
__device__ __align__(16) float    g_u[BATCH * USTRIDE + 8];
__device__ __align__(16) unsigned g_up[BATCH * USTRIDE + 8];      // (u[y],u[y-1]) fp16x2
__device__ __align__(16) unsigned g_Hp[MEM * HPAIR];              // fp16 pairs
__device__ __align__(16) unsigned g_Wp[HID * WPAIR];              // fp16 pairs
__device__ __align__(16) unsigned g_xp[(size_t)BATCH * T * XPAIR];
__device__ __align__(16) unsigned g_mp[(size_t)BATCH * T * MPAIR];
__device__ int g_flag[NFLAG];                                     // conv->gemm2 ready flags

// ---------------- helpers ----------------
__device__ __forceinline__ unsigned packh2(float a, float b) {
    __half2 t = __floats2half2_rn(a, b);
    return *reinterpret_cast<unsigned*>(&t);
}
__device__ __forceinline__ uint32_t smem_u32(const void* p) {
    uint32_t a;
    asm("{ .reg .u64 t; cvta.to.shared.u64 t, %1; cvt.u32.u64 %0, t; }" : "=r"(a) : "l"(p));
    return a;
}
__device__ __forceinline__ void cp16(uint32_t saddr, const void* g) {
    asm volatile("cp.async.cg.shared.global [%0], [%1], 16;" :: "r"(saddr), "l"(g));
}
__device__ __forceinline__ void cp_commit() {
    asm volatile("cp.async.commit_group;" ::: "memory");
}
__device__ __forceinline__ void cp_wait1() {
    asm volatile("cp.async.wait_group 1;" ::: "memory");
}
__device__ __forceinline__ void ldsm4(unsigned& r0, unsigned& r1,
                                      unsigned& r2, unsigned& r3, uint32_t a) {
    asm volatile("ldmatrix.sync.aligned.m8n8.x4.shared.b16 {%0,%1,%2,%3}, [%4];"
                 : "=r"(r0), "=r"(r1), "=r"(r2), "=r"(r3) : "r"(a));
}
// D += A(16x16) * B(16x8), fp16 in, fp32 accum
__device__ __forceinline__ void mma16816(float* c, const unsigned* a,
                                         unsigned b0, unsigned b1) {
    asm volatile(
        "mma.sync.aligned.m16n8k16.row.col.f32.f16.f16.f32 "
        "{%0,%1,%2,%3},{%4,%5,%6,%7},{%8,%9},{%0,%1,%2,%3};"
        : "+f"(c[0]), "+f"(c[1]), "+f"(c[2]), "+f"(c[3])
        : "r"(a[0]), "r"(a[1]), "r"(a[2]), "r"(a[3]), "r"(b0), "r"(b1));
}

// ---------------------------------------------------------------------------
// Front kernel: CTAs [0, UX_BLOCKS): u = relu(x@Wu) + x->fp16 pack, 2 rows/warp
// (MLP 4). CTAs beyond: pack H, W_h, and zero the conv->gemm2 flags.
// ---------------------------------------------------------------------------
__global__ __launch_bounds__(256) void k_front(const float* __restrict__ x,
                                               const float* __restrict__ Wu,
                                               const float* __restrict__ Wh,
                                               const float* __restrict__ H) {
    int bx = blockIdx.x;
    if (bx < UX_BLOCKS) {
        __shared__ float w[IN_DIM];
        int tid = threadIdx.x;
        w[tid] = Wu[tid];
        __syncthreads();
        int warp = tid >> 5, lane = tid & 31;
        int row0 = bx * 16 + warp * 2;
        const float* xr = x + (size_t)row0 * IN_DIM;
        // 4 upfront 16B loads (2 rows)
        float4 a0 = *(const float4*)(xr + lane * 4);
        float4 b0 = *(const float4*)(xr + 128 + lane * 4);
        float4 a1 = *(const float4*)(xr + 256 + lane * 4);
        float4 b1 = *(const float4*)(xr + 384 + lane * 4);
        {
            uint2 p0 = make_uint2(packh2(a0.x, a0.y), packh2(a0.z, a0.w));
            uint2 p1 = make_uint2(packh2(b0.x, b0.y), packh2(b0.z, b0.w));
            uint2 p2 = make_uint2(packh2(a1.x, a1.y), packh2(a1.z, a1.w));
            uint2 p3 = make_uint2(packh2(b1.x, b1.y), packh2(b1.z, b1.w));
            size_t rb = (size_t)row0 * XPAIR;
            *(uint2*)&g_xp[rb + 2 * lane]              = p0;
            *(uint2*)&g_xp[rb + 64 + 2 * lane]         = p1;
            *(uint2*)&g_xp[rb + XPAIR + 2 * lane]      = p2;
            *(uint2*)&g_xp[rb + XPAIR + 64 + 2 * lane] = p3;
        }
        int j0 = lane * 4;
        float s0 = a0.x * w[j0] + a0.y * w[j0 + 1] + a0.z * w[j0 + 2] + a0.w * w[j0 + 3]
                 + b0.x * w[128 + j0] + b0.y * w[128 + j0 + 1]
                 + b0.z * w[128 + j0 + 2] + b0.w * w[128 + j0 + 3];
        float s1 = a1.x * w[j0] + a1.y * w[j0 + 1] + a1.z * w[j0 + 2] + a1.w * w[j0 + 3]
                 + b1.x * w[128 + j0] + b1.y * w[128 + j0 + 1]
                 + b1.z * w[128 + j0 + 2] + b1.w * w[128 + j0 + 3];
#pragma unroll
        for (int off = 16; off; off >>= 1) {
            s0 += __shfl_xor_sync(0xffffffffu, s0, off);
            s1 += __shfl_xor_sync(0xffffffffu, s1, off);
        }
        if (lane == 0) {
            int bb = row0 >> 12, t = row0 & (T - 1);
            g_u[bb * USTRIDE + S + t]     = fmaxf(s0, 0.0f);
            g_u[bb * USTRIDE + S + t + 1] = fmaxf(s1, 0.0f);
        }
    } else {
        size_t i = (size_t)(bx - UX_BLOCKS) * 256 + threadIdx.x;
        if (i < HTOT) {
            g_Hp[i] = packh2(H[2 * i], H[2 * i + 1]);
        } else if (i < HTOT + WTOT) {
            size_t p = i - HTOT;
            g_Wp[p] = packh2(Wh[2 * p], Wh[2 * p + 1]);
        } else if (i < HTOT + WTOT + NFLAG) {
            g_flag[i - HTOT - WTOT] = 0;
        }
    }
}

// reversed pairs: up[y] = (u[y], u[y-1]) as fp16x2, pads produce exact zeros
__global__ void k_pack_u() {
    int y = blockIdx.x * 256 + threadIdx.x;
    if (y >= BATCH * USTRIDE) return;
    int local = y % USTRIDE;
    float v0 = 0.0f, v1 = 0.0f;
    if (local >= S) v0 = g_u[y];
    if (local > S)  v1 = g_u[y - 1];
    g_up[y] = packh2(v0, v1);
}

// ---------------------------------------------------------------------------
// Fused MMA kernel. bids [0, CONV_CTAS): conv; [CONV_CTAS, +G2_CTAS): gemm2.
// Conv CTAs come first in launch order -> gemm2 spin on flags cannot deadlock.
// conv stage (words): H 8704 | u 256 = 8960 ; gemm2 stage: As 4608 | Ws 4608
// Shared smem budget = max of both layouts = 110592 B, 2 CTAs/SM.
// ---------------------------------------------------------------------------
#define CV_STG 8960
#define G2_AS 4608
#define G2_STG (2 * G2_AS)                 // 9216 words
#define MMA_SMEM_BYTES (3 * G2_STG * 4)    // 110592 (>= 3*CV_STG*4 = 107520)

__global__ __launch_bounds__(256, 2) void k_mma(float* __restrict__ out) {
    extern __shared__ unsigned sm[];
    uint32_t sb = smem_u32(sm);

    int tid = threadIdx.x, lane = tid & 31, wid = tid >> 5;
    int g = lane >> 2, tig = lane & 3;
    int wm = wid & 3, wn = wid >> 2;
    int bid = blockIdx.x;

    float acc[2][8][4];
#pragma unroll
    for (int mt = 0; mt < 2; ++mt)
#pragma unroll
        for (int nt = 0; nt < 8; ++nt)
#pragma unroll
            for (int q = 0; q < 4; ++q) acc[mt][nt][q] = 0.0f;

    const int srow = tid >> 1, shalf = tid & 1;

    if (bid < CONV_CTAS) {
        // ================== CONV ==================
        // LPT: heaviest tiles (jb=31) first
        int jb = NB - 1 - (bid >> 6);
        int idx = bid & 63;
        int ks = idx & 1, b = idx >> 1;

        const size_t hrow = (size_t)(ks * 128 + srow) * HPAIR + shalf * 32;
        const uint32_t bOff = (uint32_t)((wn * 64 + ((lane >> 4) << 3) + (lane & 7)) * 68) * 4
                            + ((lane & 8) << 1);

        auto stage = [&](int i, int s) {
            if (i <= jb) {
                int l = jb - i;
                const unsigned* shh = &g_Hp[hrow + l * 64];
                uint32_t dh = sb + (uint32_t)(s * CV_STG + srow * 68 + shalf * 32) * 4;
#pragma unroll
                for (int q = 0; q < 8; ++q) cp16(dh + q * 16, shh + q * 4);
                int Wb = b * USTRIDE + i * S;
                if (tid < 64)
                    cp16(sb + (uint32_t)(s * CV_STG + 8704 + tid * 4) * 4,
                         &g_up[Wb + tid * 4]);
            }
            cp_commit();
        };

        stage(0, 0);
        stage(1, 1);
        int p = 0;
        for (int i = 0; i <= jb; ++i) {
            cp_wait1();
            __syncthreads();
            int s2 = p + 2; if (s2 >= 3) s2 -= 3;
            stage(i + 2, s2);

            unsigned* uw = sm + p * CV_STG + 8704;
            uint32_t bBase = sb + (uint32_t)(p * CV_STG) * 4 + bOff;

#pragma unroll
            for (int kk = 0; kk < 8; ++kk) {
                bool sk0 = (i == 0) && (kk > 2 * wm);
                bool sk1 = (i == 0) && (kk > 2 * wm + 1);
                unsigned ah[2][4];
#pragma unroll
                for (int mt = 0; mt < 2; ++mt) {
                    bool sk = mt ? sk1 : sk0;
                    if (!sk) {
                        int base = 128 + wm * 32 + mt * 16 + g - kk * 16 - 2 * tig;
                        ah[mt][0] = uw[base];
                        ah[mt][1] = uw[base + 8];
                        ah[mt][2] = uw[base - 8];
                        ah[mt][3] = ah[mt][0];   // Toeplitz diagonal
                    }
                }
#pragma unroll
                for (int np = 0; np < 4; ++np) {
                    unsigned rb[4];
                    ldsm4(rb[0], rb[1], rb[2], rb[3], bBase + np * (16 * 68 * 4) + kk * 32);
                    if (!sk0) {
                        mma16816(acc[0][2 * np],     ah[0], rb[0], rb[1]);
                        mma16816(acc[0][2 * np + 1], ah[0], rb[2], rb[3]);
                    }
                    if (!sk1) {
                        mma16816(acc[1][2 * np],     ah[1], rb[0], rb[1]);
                        mma16816(acc[1][2 * np + 1], ah[1], rb[2], rb[3]);
                    }
                }
            }
            if (++p == 3) p = 0;
        }

        // epilogue: m -> fp16 pairs
#pragma unroll
        for (int mt = 0; mt < 2; ++mt) {
            size_t row0 = (size_t)b * T + (size_t)jb * S + wm * 32 + mt * 16 + g;
#pragma unroll
            for (int nt = 0; nt < 8; ++nt) {
                int pp = ks * 64 + wn * 32 + nt * 4 + tig;
                g_mp[row0 * MPAIR + pp]       = packh2(acc[mt][nt][0], acc[mt][nt][1]);
                g_mp[(row0 + 8) * MPAIR + pp] = packh2(acc[mt][nt][2], acc[mt][nt][3]);
            }
        }
        // publish: all threads fence their stores, then one release-count
        __threadfence();
        __syncthreads();
        if (tid == 0) atomicAdd(&g_flag[b * NB + jb], 1);

    } else {
        // ================== GEMM2 ==================
        // order jb descending to match conv completion (LPT)
        int bid2 = bid - CONV_CTAS;
        int jb = NB - 1 - (bid2 >> 7);
        int rem = bid2 & 127;
        int b = rem >> 2, ob = rem & 3;
        int tb = b * NB + jb;
        const int fidx = tb;

        const size_t arow0 = ((size_t)tb * 128 + srow) * 128 + shalf * 16;
        const size_t wrow0 = (size_t)(ob * 128 + srow) * WPAIR + shalf * 16;

        const uint32_t aOff = (uint32_t)((wm * 32 + ((lane & 8) ? 8 : 0) + (lane & 7)) * 36) * 4
                            + ((lane & 16) ? 16 : 0);
        const uint32_t bOff = (uint32_t)((wn * 64 + ((lane >> 4) << 3) + (lane & 7)) * 36) * 4
                            + ((lane & 8) << 1);

        // pipeline position pos -> logical chunk (pos+4)&7: x chunks (4..7) first,
        // m chunks (0..3) last; m staging starts at loop c==2 (after flag wait).
        auto stage = [&](int pos, int s) {
            if (pos < 8) {
                int cc = (pos + 4) & 7;
                const unsigned* pa = (cc < 4) ? &g_mp[arow0 + cc * 32]
                                              : &g_xp[arow0 + (cc - 4) * 32];
                const unsigned* pw = &g_Wp[wrow0 + cc * 32];
                uint32_t d0 = sb + (uint32_t)(s * G2_STG + srow * 36 + shalf * 16) * 4;
#pragma unroll
                for (int q = 0; q < 4; ++q) {
                    cp16(d0 + q * 16,             pa + q * 4);
                    cp16(d0 + G2_AS * 4 + q * 16, pw + q * 4);
                }
            }
            cp_commit();
        };

        stage(0, 0);
        stage(1, 1);
        int p = 0;
        for (int c = 0; c < 8; ++c) {
            cp_wait1();
            __syncthreads();
            if (c == 2) {      // next stage is the first m chunk: wait for conv
                if (tid == 0) {
                    while (atomicAdd(&g_flag[fidx], 0) < 2) __nanosleep(200);
                }
                __syncthreads();
                __threadfence();
            }
            int s2 = p + 2; if (s2 >= 3) s2 -= 3;
            stage(c + 2, s2);

            uint32_t aBase = sb + (uint32_t)(p * G2_STG) * 4 + aOff;
            uint32_t bBase = sb + (uint32_t)(p * G2_STG + G2_AS) * 4 + bOff;

#pragma unroll
            for (int kk = 0; kk < 4; ++kk) {
                unsigned ah[2][4];
#pragma unroll
                for (int mt = 0; mt < 2; ++mt)
                    ldsm4(ah[mt][0], ah[mt][1], ah[mt][2], ah[mt][3],
                          aBase + mt * (16 * 36 * 4) + kk * 32);
#pragma unroll
                for (int np = 0; np < 4; ++np) {
                    unsigned rb[4];
                    ldsm4(rb[0], rb[1], rb[2], rb[3], bBase + np * (16 * 36 * 4) + kk * 32);
                    mma16816(acc[0][2 * np],     ah[0], rb[0], rb[1]);
                    mma16816(acc[0][2 * np + 1], ah[0], rb[2], rb[3]);
                    mma16816(acc[1][2 * np],     ah[1], rb[0], rb[1]);
                    mma16816(acc[1][2 * np + 1], ah[1], rb[2], rb[3]);
                }
            }
            if (++p == 3) p = 0;
        }

        // epilogue: relu, write h and h_n
        const size_t HSIZE = (size_t)BATCH * T * HID;
#pragma unroll
        for (int mt = 0; mt < 2; ++mt) {
            size_t row0 = (size_t)tb * 128 + wm * 32 + mt * 16 + g;
#pragma unroll
            for (int nt = 0; nt < 8; ++nt) {
                int col = ob * 128 + wn * 64 + nt * 8 + tig * 2;
                float2 v0 = make_float2(fmaxf(acc[mt][nt][0], 0.f), fmaxf(acc[mt][nt][1], 0.f));
                float2 v1 = make_float2(fmaxf(acc[mt][nt][2], 0.f), fmaxf(acc[mt][nt][3], 0.f));
                *(float2*)&out[row0 * HID + col] = v0;
                *(float2*)&out[(row0 + 8) * HID + col] = v1;
                if ((row0 & (size_t)(T - 1)) == (size_t)(T - 1))
                    *(float2*)&out[HSIZE + (row0 >> 12) * HID + col] = v0;
                if (((row0 + 8) & (size_t)(T - 1)) == (size_t)(T - 1))
                    *(float2*)&out[HSIZE + ((row0 + 8) >> 12) * HID + col] = v1;
            }
        }
    }
}

// ---------------------------------------------------------------------------
extern "C" void kernel_launch(void* const* d_in, const int* in_sizes, int n_in,
                              void* d_out, int out_size) {
    const float* x  = (const float*)d_in[0];   // (32, 4096, 256)
    const float* Wu = (const float*)d_in[1];   // (1, 256)
    const float* Wh = (const float*)d_in[2];   // (512, 512)
    const float* H  = (const float*)d_in[3];   // (256, 4096)
    float* out = (float*)d_out;

    (void)in_sizes; (void)n_in; (void)out_size;

    static int smem_set = 0;
    if (!smem_set) {
        cudaFuncSetAttribute(k_mma, cudaFuncAttributeMaxDynamicSharedMemorySize,
                             MMA_SMEM_BYTES);
        smem_set = 1;
    }

    k_front<<<UX_BLOCKS + PREP_BLOCKS, 256>>>(x, Wu, Wh, H);
    k_pack_u<<<(BATCH * USTRIDE + 255) / 256, 256>>>();
    k_mma<<<CONV_CTAS + G2_CTAS, 256, MMA_SMEM_BYTES>>>(out);
}

// round 15
// speedup vs baseline: 1.0124x; 1.0124x over previous
#include <cuda_runtime.h>
#include <cuda_fp16.h>
#include <cstdint>

#define BATCH 32
#define T 4096
#define IN_DIM 256
#define MEM 256
#define HID 512
#define S 128
#define NB 32
#define USTRIDE (T + S)
#define HPAIR (T / 2)               // 2048 pairs per H row
#define MPAIR (MEM / 2)             // 128
#define XPAIR (IN_DIM / 2)          // 128
#define WPAIR ((MEM + IN_DIM) / 2)  // 256

#define UX_BLOCKS (BATCH * T / 16)                  // 8192 CTAs (2 rows/warp)
#define HTOT ((size_t)MEM * HPAIR)                  // 524288
#define WTOT ((size_t)HID * WPAIR)                  // 131072
#define PREP_BLOCKS ((int)((HTOT + WTOT + 255) / 256))  // 2560

// ---------------- scratch (device globals, 16B aligned for cp.async) --------
__device__ __align__(16) float    g_u[BATCH * USTRIDE + 8];
__device__ __align__(16) unsigned g_up[BATCH * USTRIDE + 8];      // (u[y],u[y-1]) fp16x2
__device__ __align__(16) unsigned g_Hp[MEM * HPAIR];              // fp16 pairs
__device__ __align__(16) unsigned g_Wp[HID * WPAIR];              // fp16 pairs
__device__ __align__(16) unsigned g_xp[(size_t)BATCH * T * XPAIR];
__device__ __align__(16) unsigned g_mp[(size_t)BATCH * T * MPAIR];

// ---------------- helpers ----------------
__device__ __forceinline__ unsigned packh2(float a, float b) {
    __half2 t = __floats2half2_rn(a, b);
    return *reinterpret_cast<unsigned*>(&t);
}
__device__ __forceinline__ uint32_t smem_u32(const void* p) {
    uint32_t a;
    asm("{ .reg .u64 t; cvta.to.shared.u64 t, %1; cvt.u32.u64 %0, t; }" : "=r"(a) : "l"(p));
    return a;
}
__device__ __forceinline__ void cp16(uint32_t saddr, const void* g) {
    asm volatile("cp.async.cg.shared.global [%0], [%1], 16;" :: "r"(saddr), "l"(g));
}
__device__ __forceinline__ void cp_commit() {
    asm volatile("cp.async.commit_group;" ::: "memory");
}
__device__ __forceinline__ void cp_wait1() {
    asm volatile("cp.async.wait_group 1;" ::: "memory");
}
__device__ __forceinline__ void ldsm4(unsigned& r0, unsigned& r1,
                                      unsigned& r2, unsigned& r3, uint32_t a) {
    asm volatile("ldmatrix.sync.aligned.m8n8.x4.shared.b16 {%0,%1,%2,%3}, [%4];"
                 : "=r"(r0), "=r"(r1), "=r"(r2), "=r"(r3) : "r"(a));
}
// D += A(16x16) * B(16x8), fp16 in, fp32 accum
__device__ __forceinline__ void mma16816(float* c, const unsigned* a,
                                         unsigned b0, unsigned b1) {
    asm volatile(
        "mma.sync.aligned.m16n8k16.row.col.f32.f16.f16.f32 "
        "{%0,%1,%2,%3},{%4,%5,%6,%7},{%8,%9},{%0,%1,%2,%3};"
        : "+f"(c[0]), "+f"(c[1]), "+f"(c[2]), "+f"(c[3])
        : "r"(a[0]), "r"(a[1]), "r"(a[2]), "r"(a[3]), "r"(b0), "r"(b1));
}

// ---------------------------------------------------------------------------
// Front kernel: CTAs [0, UX_BLOCKS): u = relu(x@Wu) + x->fp16 pack, 2 rows/warp
// (MLP 4, measured 75% of HBM spec). CTAs beyond: pack H, W_h.
// ---------------------------------------------------------------------------
__global__ __launch_bounds__(256) void k_front(const float* __restrict__ x,
                                               const float* __restrict__ Wu,
                                               const float* __restrict__ Wh,
                                               const float* __restrict__ H) {
    int bx = blockIdx.x;
    if (bx < UX_BLOCKS) {
        __shared__ float w[IN_DIM];
        int tid = threadIdx.x;
        w[tid] = Wu[tid];
        __syncthreads();
        int warp = tid >> 5, lane = tid & 31;
        int row0 = bx * 16 + warp * 2;
        const float* xr = x + (size_t)row0 * IN_DIM;
        float4 a0 = *(const float4*)(xr + lane * 4);
        float4 b0 = *(const float4*)(xr + 128 + lane * 4);
        float4 a1 = *(const float4*)(xr + 256 + lane * 4);
        float4 b1 = *(const float4*)(xr + 384 + lane * 4);
        {
            uint2 p0 = make_uint2(packh2(a0.x, a0.y), packh2(a0.z, a0.w));
            uint2 p1 = make_uint2(packh2(b0.x, b0.y), packh2(b0.z, b0.w));
            uint2 p2 = make_uint2(packh2(a1.x, a1.y), packh2(a1.z, a1.w));
            uint2 p3 = make_uint2(packh2(b1.x, b1.y), packh2(b1.z, b1.w));
            size_t rb = (size_t)row0 * XPAIR;
            *(uint2*)&g_xp[rb + 2 * lane]              = p0;
            *(uint2*)&g_xp[rb + 64 + 2 * lane]         = p1;
            *(uint2*)&g_xp[rb + XPAIR + 2 * lane]      = p2;
            *(uint2*)&g_xp[rb + XPAIR + 64 + 2 * lane] = p3;
        }
        int j0 = lane * 4;
        float s0 = a0.x * w[j0] + a0.y * w[j0 + 1] + a0.z * w[j0 + 2] + a0.w * w[j0 + 3]
                 + b0.x * w[128 + j0] + b0.y * w[128 + j0 + 1]
                 + b0.z * w[128 + j0 + 2] + b0.w * w[128 + j0 + 3];
        float s1 = a1.x * w[j0] + a1.y * w[j0 + 1] + a1.z * w[j0 + 2] + a1.w * w[j0 + 3]
                 + b1.x * w[128 + j0] + b1.y * w[128 + j0 + 1]
                 + b1.z * w[128 + j0 + 2] + b1.w * w[128 + j0 + 3];
#pragma unroll
        for (int off = 16; off; off >>= 1) {
            s0 += __shfl_xor_sync(0xffffffffu, s0, off);
            s1 += __shfl_xor_sync(0xffffffffu, s1, off);
        }
        if (lane == 0) {
            int bb = row0 >> 12, t = row0 & (T - 1);
            g_u[bb * USTRIDE + S + t]     = fmaxf(s0, 0.0f);
            g_u[bb * USTRIDE + S + t + 1] = fmaxf(s1, 0.0f);
        }
    } else {
        size_t i = (size_t)(bx - UX_BLOCKS) * 256 + threadIdx.x;
        if (i < HTOT) {
            g_Hp[i] = packh2(H[2 * i], H[2 * i + 1]);
        } else if (i < HTOT + WTOT) {
            size_t p = i - HTOT;
            g_Wp[p] = packh2(Wh[2 * p], Wh[2 * p + 1]);
        }
    }
}

// reversed pairs: up[y] = (u[y], u[y-1]) as fp16x2, pads produce exact zeros
__global__ void k_pack_u() {
    int y = blockIdx.x * 256 + threadIdx.x;
    if (y >= BATCH * USTRIDE) return;
    int local = y % USTRIDE;
    float v0 = 0.0f, v1 = 0.0f;
    if (local >= S) v0 = g_u[y];
    if (local > S)  v1 = g_u[y - 1];
    g_up[y] = packh2(v0, v1);
}

// ---------------------------------------------------------------------------
// Conv: m tile 128 tau x 128 k, pure fp16 single-term HMMA.
// B fragments via ldmatrix.x4; A (Toeplitz) via scalar LDS + diag sharing.
// LPT CTA order; i==0 triangular skip; 3-stage cp.async pipeline.
// Stage layout (words): H 8704 | u 256  = 8960
// ---------------------------------------------------------------------------
#define CV_STG 8960
#define CV_SMEM_BYTES (3 * CV_STG * 4)   // 107520

__global__ __launch_bounds__(256, 2) void k_conv_hmma() {
    extern __shared__ unsigned sm[];
    uint32_t sb = smem_u32(sm);

    int tid = threadIdx.x, lane = tid & 31, wid = tid >> 5;
    int g = lane >> 2, tig = lane & 3;
    int wm = wid & 3, wn = wid >> 2;

    // LPT: heaviest tiles (jb=31) occupy the first 64 bids, etc.
    int bid = blockIdx.x + 32 * (blockIdx.y + 2 * blockIdx.z);
    int jb = NB - 1 - (bid >> 6);
    int idx = bid & 63;
    int ks = idx & 1, b = idx >> 1;

    float acc[2][8][4];
#pragma unroll
    for (int mt = 0; mt < 2; ++mt)
#pragma unroll
        for (int nt = 0; nt < 8; ++nt)
#pragma unroll
            for (int q = 0; q < 4; ++q) acc[mt][nt][q] = 0.0f;

    const int srow = tid >> 1, shalf = tid & 1;
    const size_t hrow = (size_t)(ks * 128 + srow) * HPAIR + shalf * 32;

    const uint32_t bOff = (uint32_t)((wn * 64 + ((lane >> 4) << 3) + (lane & 7)) * 68) * 4
                        + ((lane & 8) << 1);

    auto stage = [&](int i, int s) {
        if (i <= jb) {
            int l = jb - i;
            const unsigned* shh = &g_Hp[hrow + l * 64];
            uint32_t dh = sb + (uint32_t)(s * CV_STG + srow * 68 + shalf * 32) * 4;
#pragma unroll
            for (int q = 0; q < 8; ++q) cp16(dh + q * 16, shh + q * 4);
            int Wb = b * USTRIDE + i * S;    // window start; front pad covers t<0
            if (tid < 64)
                cp16(sb + (uint32_t)(s * CV_STG + 8704 + tid * 4) * 4,
                     &g_up[Wb + tid * 4]);
        }
        cp_commit();
    };

    stage(0, 0);
    stage(1, 1);
    int p = 0;
    for (int i = 0; i <= jb; ++i) {
        cp_wait1();
        __syncthreads();
        int s2 = p + 2; if (s2 >= 3) s2 -= 3;
        stage(i + 2, s2);

        unsigned* uw = sm + p * CV_STG + 8704;
        uint32_t bBase = sb + (uint32_t)(p * CV_STG) * 4 + bOff;

#pragma unroll
        for (int kk = 0; kk < 8; ++kk) {
            bool sk0 = (i == 0) && (kk > 2 * wm);
            bool sk1 = (i == 0) && (kk > 2 * wm + 1);
            unsigned ah[2][4];
#pragma unroll
            for (int mt = 0; mt < 2; ++mt) {
                bool sk = mt ? sk1 : sk0;
                if (!sk) {
                    int base = 128 + wm * 32 + mt * 16 + g - kk * 16 - 2 * tig;
                    ah[mt][0] = uw[base];
                    ah[mt][1] = uw[base + 8];
                    ah[mt][2] = uw[base - 8];
                    ah[mt][3] = ah[mt][0];   // Toeplitz diagonal
                }
            }
#pragma unroll
            for (int np = 0; np < 4; ++np) {
                unsigned rb[4];
                ldsm4(rb[0], rb[1], rb[2], rb[3], bBase + np * (16 * 68 * 4) + kk * 32);
                if (!sk0) {
                    mma16816(acc[0][2 * np],     ah[0], rb[0], rb[1]);
                    mma16816(acc[0][2 * np + 1], ah[0], rb[2], rb[3]);
                }
                if (!sk1) {
                    mma16816(acc[1][2 * np],     ah[1], rb[0], rb[1]);
                    mma16816(acc[1][2 * np + 1], ah[1], rb[2], rb[3]);
                }
            }
        }
        if (++p == 3) p = 0;
    }

    // epilogue: m -> fp16 pairs for gemm2
#pragma unroll
    for (int mt = 0; mt < 2; ++mt) {
        size_t row0 = (size_t)b * T + (size_t)jb * S + wm * 32 + mt * 16 + g;
#pragma unroll
        for (int nt = 0; nt < 8; ++nt) {
            int pp = ks * 64 + wn * 32 + nt * 4 + tig;
            g_mp[row0 * MPAIR + pp]       = packh2(acc[mt][nt][0], acc[mt][nt][1]);
            g_mp[(row0 + 8) * MPAIR + pp] = packh2(acc[mt][nt][2], acc[mt][nt][3]);
        }
    }
}

// ---------------------------------------------------------------------------
// GEMM2: h = relu([m|x] @ W_h^T). CTA = 128 rows x 128 outs, 8 K-chunks of 64.
// A and B fragments via ldmatrix.x4. 3-stage pipeline, one sync per iter.
// Stage (words): As 4608 | Ws 4608
// ---------------------------------------------------------------------------
#define G2_AS 4608
#define G2_STG (2 * G2_AS)               // 9216 words
#define G2_SMEM_BYTES (3 * G2_STG * 4)   // 110592

__global__ __launch_bounds__(256, 2) void k_gemm2_hmma(float* __restrict__ out) {
    extern __shared__ unsigned sm[];
    uint32_t sb = smem_u32(sm);

    int tid = threadIdx.x, lane = tid & 31, wid = tid >> 5;
    int g = lane >> 2, tig = lane & 3;
    int wm = wid & 3, wn = wid >> 2;
    int ob = blockIdx.x, tb = blockIdx.y;

    float acc[2][8][4];
#pragma unroll
    for (int mt = 0; mt < 2; ++mt)
#pragma unroll
        for (int nt = 0; nt < 8; ++nt)
#pragma unroll
            for (int q = 0; q < 4; ++q) acc[mt][nt][q] = 0.0f;

    const int srow = tid >> 1, shalf = tid & 1;
    const size_t arow0 = ((size_t)tb * 128 + srow) * 128 + shalf * 16;
    const size_t wrow0 = (size_t)(ob * 128 + srow) * WPAIR + shalf * 16;

    const uint32_t aOff = (uint32_t)((wm * 32 + ((lane & 8) ? 8 : 0) + (lane & 7)) * 36) * 4
                        + ((lane & 16) ? 16 : 0);
    const uint32_t bOff = (uint32_t)((wn * 64 + ((lane >> 4) << 3) + (lane & 7)) * 36) * 4
                        + ((lane & 8) << 1);

    auto stage = [&](int c, int s) {
        if (c < 8) {
            const unsigned* pa = (c < 4) ? &g_mp[arow0 + c * 32]
                                         : &g_xp[arow0 + (c - 4) * 32];
            const unsigned* pw = &g_Wp[wrow0 + c * 32];
            uint32_t d0 = sb + (uint32_t)(s * G2_STG + srow * 36 + shalf * 16) * 4;
#pragma unroll
            for (int q = 0; q < 4; ++q) {
                cp16(d0 + q * 16,             pa + q * 4);
                cp16(d0 + G2_AS * 4 + q * 16, pw + q * 4);
            }
        }
        cp_commit();
    };

    stage(0, 0);
    stage(1, 1);
    int p = 0;
    for (int c = 0; c < 8; ++c) {
        cp_wait1();
        __syncthreads();
        int s2 = p + 2; if (s2 >= 3) s2 -= 3;
        stage(c + 2, s2);

        uint32_t aBase = sb + (uint32_t)(p * G2_STG) * 4 + aOff;
        uint32_t bBase = sb + (uint32_t)(p * G2_STG + G2_AS) * 4 + bOff;

#pragma unroll
        for (int kk = 0; kk < 4; ++kk) {
            unsigned ah[2][4];
#pragma unroll
            for (int mt = 0; mt < 2; ++mt)
                ldsm4(ah[mt][0], ah[mt][1], ah[mt][2], ah[mt][3],
                      aBase + mt * (16 * 36 * 4) + kk * 32);
#pragma unroll
            for (int np = 0; np < 4; ++np) {
                unsigned rb[4];
                ldsm4(rb[0], rb[1], rb[2], rb[3], bBase + np * (16 * 36 * 4) + kk * 32);
                mma16816(acc[0][2 * np],     ah[0], rb[0], rb[1]);
                mma16816(acc[0][2 * np + 1], ah[0], rb[2], rb[3]);
                mma16816(acc[1][2 * np],     ah[1], rb[0], rb[1]);
                mma16816(acc[1][2 * np + 1], ah[1], rb[2], rb[3]);
            }
        }
        if (++p == 3) p = 0;
    }

    // epilogue: relu, write h and h_n
    const size_t HSIZE = (size_t)BATCH * T * HID;
#pragma unroll
    for (int mt = 0; mt < 2; ++mt) {
        size_t row0 = (size_t)tb * 128 + wm * 32 + mt * 16 + g;
#pragma unroll
        for (int nt = 0; nt < 8; ++nt) {
            int col = ob * 128 + wn * 64 + nt * 8 + tig * 2;
            float2 v0 = make_float2(fmaxf(acc[mt][nt][0], 0.f), fmaxf(acc[mt][nt][1], 0.f));
            float2 v1 = make_float2(fmaxf(acc[mt][nt][2], 0.f), fmaxf(acc[mt][nt][3], 0.f));
            *(float2*)&out[row0 * HID + col] = v0;
            *(float2*)&out[(row0 + 8) * HID + col] = v1;
            if ((row0 & (size_t)(T - 1)) == (size_t)(T - 1))
                *(float2*)&out[HSIZE + (row0 >> 12) * HID + col] = v0;
            if (((row0 + 8) & (size_t)(T - 1)) == (size_t)(T - 1))
                *(float2*)&out[HSIZE + ((row0 + 8) >> 12) * HID + col] = v1;
        }
    }
}

// ---------------------------------------------------------------------------
extern "C" void kernel_launch(void* const* d_in, const int* in_sizes, int n_in,
                              void* d_out, int out_size) {
    const float* x  = (const float*)d_in[0];   // (32, 4096, 256)
    const float* Wu = (const float*)d_in[1];   // (1, 256)
    const float* Wh = (const float*)d_in[2];   // (512, 512)
    const float* H  = (const float*)d_in[3];   // (256, 4096)
    float* out = (float*)d_out;

    (void)in_sizes; (void)n_in; (void)out_size;

    static int smem_set = 0;
    if (!smem_set) {
        cudaFuncSetAttribute(k_conv_hmma, cudaFuncAttributeMaxDynamicSharedMemorySize,
                             CV_SMEM_BYTES);
        cudaFuncSetAttribute(k_gemm2_hmma, cudaFuncAttributeMaxDynamicSharedMemorySize,
                             G2_SMEM_BYTES);
        smem_set = 1;
    }

    k_front<<<UX_BLOCKS + PREP_BLOCKS, 256>>>(x, Wu, Wh, H);
    k_pack_u<<<(BATCH * USTRIDE + 255) / 256, 256>>>();
    k_conv_hmma<<<dim3(NB, 2, BATCH), 256, CV_SMEM_BYTES>>>();
    k_gemm2_hmma<<<dim3(HID / 128, BATCH * T / 128), 256, G2_SMEM_BYTES>>>(out);
}

// round 16
// speedup vs baseline: 1.1920x; 1.1773x over previous
#include <cuda_runtime.h>
#include <cuda_fp16.h>
#include <cstdint>

#define BATCH 32
#define T 4096
#define IN_DIM 256
#define MEM 256
#define HID 512
#define S 128
#define NB 32
#define USTRIDE (T + S)
#define HPAIR (T / 2)               // 2048 pairs per H row
#define MPAIR (MEM / 2)             // 128
#define XPAIR (IN_DIM / 2)          // 128
#define WPAIR ((MEM + IN_DIM) / 2)  // 256

#define UX_BLOCKS (BATCH * T / 16)                  // 8192 CTAs (2 rows/warp)
#define HTOT ((size_t)MEM * HPAIR)                  // 524288
#define WTOT ((size_t)HID * WPAIR)                  // 131072
#define PREP_BLOCKS ((int)((HTOT + WTOT + 255) / 256))  // 2560

// ---------------- scratch (device globals, 16B aligned for cp.async) --------
__device__ __align__(16) float    g_u[BATCH * USTRIDE + 8];
__device__ __align__(16) unsigned g_up[BATCH * USTRIDE + 8];      // (u[y],u[y-1]) fp16x2
__device__ __align__(16) unsigned g_Hp[MEM * HPAIR];              // fp16 pairs
__device__ __align__(16) unsigned g_Wp[HID * WPAIR];              // fp16 pairs
__device__ __align__(16) unsigned g_xp[(size_t)BATCH * T * XPAIR];
__device__ __align__(16) unsigned g_mp[(size_t)BATCH * T * MPAIR];

// ---------------- helpers ----------------
__device__ __forceinline__ unsigned packh2(float a, float b) {
    __half2 t = __floats2half2_rn(a, b);
    return *reinterpret_cast<unsigned*>(&t);
}
__device__ __forceinline__ uint32_t smem_u32(const void* p) {
    uint32_t a;
    asm("{ .reg .u64 t; cvta.to.shared.u64 t, %1; cvt.u32.u64 %0, t; }" : "=r"(a) : "l"(p));
    return a;
}
__device__ __forceinline__ void cp16(uint32_t saddr, const void* g) {
    asm volatile("cp.async.cg.shared.global [%0], [%1], 16;" :: "r"(saddr), "l"(g));
}
__device__ __forceinline__ void cp_commit() {
    asm volatile("cp.async.commit_group;" ::: "memory");
}
__device__ __forceinline__ void cp_wait1() {
    asm volatile("cp.async.wait_group 1;" ::: "memory");
}
__device__ __forceinline__ void ldsm4(unsigned& r0, unsigned& r1,
                                      unsigned& r2, unsigned& r3, uint32_t a) {
    asm volatile("ldmatrix.sync.aligned.m8n8.x4.shared.b16 {%0,%1,%2,%3}, [%4];"
                 : "=r"(r0), "=r"(r1), "=r"(r2), "=r"(r3) : "r"(a));
}
// D += A(16x16) * B(16x8), fp16 in, fp32 accum
__device__ __forceinline__ void mma16816(float* c, const unsigned* a,
                                         unsigned b0, unsigned b1) {
    asm volatile(
        "mma.sync.aligned.m16n8k16.row.col.f32.f16.f16.f32 "
        "{%0,%1,%2,%3},{%4,%5,%6,%7},{%8,%9},{%0,%1,%2,%3};"
        : "+f"(c[0]), "+f"(c[1]), "+f"(c[2]), "+f"(c[3])
        : "r"(a[0]), "r"(a[1]), "r"(a[2]), "r"(a[3]), "r"(b0), "r"(b1));
}

// ---------------------------------------------------------------------------
// Front kernel: CTAs [0, UX_BLOCKS): u = relu(x@Wu) + x->fp16 pack, 2 rows/warp.
// CTAs beyond: pack H, W_h.
// ---------------------------------------------------------------------------
__global__ __launch_bounds__(256) void k_front(const float* __restrict__ x,
                                               const float* __restrict__ Wu,
                                               const float* __restrict__ Wh,
                                               const float* __restrict__ H) {
    int bx = blockIdx.x;
    if (bx < UX_BLOCKS) {
        __shared__ float w[IN_DIM];
        int tid = threadIdx.x;
        w[tid] = Wu[tid];
        __syncthreads();
        int warp = tid >> 5, lane = tid & 31;
        int row0 = bx * 16 + warp * 2;
        const float* xr = x + (size_t)row0 * IN_DIM;
        float4 a0 = *(const float4*)(xr + lane * 4);
        float4 b0 = *(const float4*)(xr + 128 + lane * 4);
        float4 a1 = *(const float4*)(xr + 256 + lane * 4);
        float4 b1 = *(const float4*)(xr + 384 + lane * 4);
        {
            uint2 p0 = make_uint2(packh2(a0.x, a0.y), packh2(a0.z, a0.w));
            uint2 p1 = make_uint2(packh2(b0.x, b0.y), packh2(b0.z, b0.w));
            uint2 p2 = make_uint2(packh2(a1.x, a1.y), packh2(a1.z, a1.w));
            uint2 p3 = make_uint2(packh2(b1.x, b1.y), packh2(b1.z, b1.w));
            size_t rb = (size_t)row0 * XPAIR;
            *(uint2*)&g_xp[rb + 2 * lane]              = p0;
            *(uint2*)&g_xp[rb + 64 + 2 * lane]         = p1;
            *(uint2*)&g_xp[rb + XPAIR + 2 * lane]      = p2;
            *(uint2*)&g_xp[rb + XPAIR + 64 + 2 * lane] = p3;
        }
        int j0 = lane * 4;
        float s0 = a0.x * w[j0] + a0.y * w[j0 + 1] + a0.z * w[j0 + 2] + a0.w * w[j0 + 3]
                 + b0.x * w[128 + j0] + b0.y * w[128 + j0 + 1]
                 + b0.z * w[128 + j0 + 2] + b0.w * w[128 + j0 + 3];
        float s1 = a1.x * w[j0] + a1.y * w[j0 + 1] + a1.z * w[j0 + 2] + a1.w * w[j0 + 3]
                 + b1.x * w[128 + j0] + b1.y * w[128 + j0 + 1]
                 + b1.z * w[128 + j0 + 2] + b1.w * w[128 + j0 + 3];
#pragma unroll
        for (int off = 16; off; off >>= 1) {
            s0 += __shfl_xor_sync(0xffffffffu, s0, off);
            s1 += __shfl_xor_sync(0xffffffffu, s1, off);
        }
        if (lane == 0) {
            int bb = row0 >> 12, t = row0 & (T - 1);
            g_u[bb * USTRIDE + S + t]     = fmaxf(s0, 0.0f);
            g_u[bb * USTRIDE + S + t + 1] = fmaxf(s1, 0.0f);
        }
    } else {
        size_t i = (size_t)(bx - UX_BLOCKS) * 256 + threadIdx.x;
        if (i < HTOT) {
            g_Hp[i] = packh2(H[2 * i], H[2 * i + 1]);
        } else if (i < HTOT + WTOT) {
            size_t p = i - HTOT;
            g_Wp[p] = packh2(Wh[2 * p], Wh[2 * p + 1]);
        }
    }
}

// reversed pairs: up[y] = (u[y], u[y-1]) as fp16x2, pads produce exact zeros
__global__ void k_pack_u() {
    int y = blockIdx.x * 256 + threadIdx.x;
    if (y >= BATCH * USTRIDE) return;
    int local = y % USTRIDE;
    float v0 = 0.0f, v1 = 0.0f;
    if (local >= S) v0 = g_u[y];
    if (local > S)  v1 = g_u[y - 1];
    g_up[y] = packh2(v0, v1);
}

// ---------------------------------------------------------------------------
// Conv: m tile 128 tau x 128 k, 512 threads (16 warps, 32x32 warp tiles).
// B via ldmatrix.x4; A (Toeplitz) via scalar LDS + diag sharing.
// LPT order; i==0 triangular skip; 3-stage cp.async pipeline.
// Stage layout (words): H 8704 | u 256  = 8960
// ---------------------------------------------------------------------------
#define CV_STG 8960
#define CV_SMEM_BYTES (3 * CV_STG * 4)   // 107520

__global__ __launch_bounds__(512, 2) void k_conv_hmma() {
    extern __shared__ unsigned sm[];
    uint32_t sb = smem_u32(sm);

    int tid = threadIdx.x, lane = tid & 31, wid = tid >> 5;   // wid 0..15
    int g = lane >> 2, tig = lane & 3;
    int wm = wid & 3, wn = wid >> 2;                          // 32 rows x 32 cols

    int bid = blockIdx.x + 32 * (blockIdx.y + 2 * blockIdx.z);
    int jb = NB - 1 - (bid >> 6);
    int idx = bid & 63;
    int ks = idx & 1, b = idx >> 1;

    float acc[2][4][4];
#pragma unroll
    for (int mt = 0; mt < 2; ++mt)
#pragma unroll
        for (int nt = 0; nt < 4; ++nt)
#pragma unroll
            for (int q = 0; q < 4; ++q) acc[mt][nt][q] = 0.0f;

    const int srow = tid >> 2, sq = tid & 3;    // 128 rows x 4 quarters
    const size_t hrow = (size_t)(ks * 128 + srow) * HPAIR + sq * 16;

    // ldmatrix per-lane offset into H tile (stride 68 words)
    const uint32_t bOff = (uint32_t)((wn * 32 + ((lane >> 4) << 3) + (lane & 7)) * 68) * 4
                        + ((lane & 8) << 1);

    auto stage = [&](int i, int s) {
        if (i <= jb) {
            int l = jb - i;
            const unsigned* shh = &g_Hp[hrow + l * 64];
            uint32_t dh = sb + (uint32_t)(s * CV_STG + srow * 68 + sq * 16) * 4;
#pragma unroll
            for (int q = 0; q < 4; ++q) cp16(dh + q * 16, shh + q * 4);
            int Wb = b * USTRIDE + i * S;    // window start; front pad covers t<0
            if (tid < 64)
                cp16(sb + (uint32_t)(s * CV_STG + 8704 + tid * 4) * 4,
                     &g_up[Wb + tid * 4]);
        }
        cp_commit();
    };

    stage(0, 0);
    stage(1, 1);
    int p = 0;
    for (int i = 0; i <= jb; ++i) {
        cp_wait1();
        __syncthreads();
        int s2 = p + 2; if (s2 >= 3) s2 -= 3;
        stage(i + 2, s2);

        unsigned* uw = sm + p * CV_STG + 8704;
        uint32_t bBase = sb + (uint32_t)(p * CV_STG) * 4 + bOff;

#pragma unroll
        for (int kk = 0; kk < 8; ++kk) {
            bool sk0 = (i == 0) && (kk > 2 * wm);
            bool sk1 = (i == 0) && (kk > 2 * wm + 1);
            unsigned ah[2][4];
#pragma unroll
            for (int mt = 0; mt < 2; ++mt) {
                bool sk = mt ? sk1 : sk0;
                if (!sk) {
                    int base = 128 + wm * 32 + mt * 16 + g - kk * 16 - 2 * tig;
                    ah[mt][0] = uw[base];
                    ah[mt][1] = uw[base + 8];
                    ah[mt][2] = uw[base - 8];
                    ah[mt][3] = ah[mt][0];   // Toeplitz diagonal
                }
            }
#pragma unroll
            for (int np = 0; np < 2; ++np) {   // 2 ldsm4 cover 32 cols
                unsigned rb[4];
                ldsm4(rb[0], rb[1], rb[2], rb[3], bBase + np * (16 * 68 * 4) + kk * 32);
                if (!sk0) {
                    mma16816(acc[0][2 * np],     ah[0], rb[0], rb[1]);
                    mma16816(acc[0][2 * np + 1], ah[0], rb[2], rb[3]);
                }
                if (!sk1) {
                    mma16816(acc[1][2 * np],     ah[1], rb[0], rb[1]);
                    mma16816(acc[1][2 * np + 1], ah[1], rb[2], rb[3]);
                }
            }
        }
        if (++p == 3) p = 0;
    }

    // epilogue: m -> fp16 pairs for gemm2
#pragma unroll
    for (int mt = 0; mt < 2; ++mt) {
        size_t row0 = (size_t)b * T + (size_t)jb * S + wm * 32 + mt * 16 + g;
#pragma unroll
        for (int nt = 0; nt < 4; ++nt) {
            int pp = ks * 64 + wn * 16 + nt * 4 + tig;
            g_mp[row0 * MPAIR + pp]       = packh2(acc[mt][nt][0], acc[mt][nt][1]);
            g_mp[(row0 + 8) * MPAIR + pp] = packh2(acc[mt][nt][2], acc[mt][nt][3]);
        }
    }
}

// ---------------------------------------------------------------------------
// GEMM2: h = relu([m|x] @ W_h^T). CTA = 128 rows x 128 outs, 512 threads
// (16 warps, 32x32 warp tiles), 8 K-chunks of 64, ldmatrix for A and B.
// 3-stage pipeline. Stage (words): As 4608 | Ws 4608
// ---------------------------------------------------------------------------
#define G2_AS 4608
#define G2_STG (2 * G2_AS)               // 9216 words
#define G2_SMEM_BYTES (3 * G2_STG * 4)   // 110592

__global__ __launch_bounds__(512, 2) void k_gemm2_hmma(float* __restrict__ out) {
    extern __shared__ unsigned sm[];
    uint32_t sb = smem_u32(sm);

    int tid = threadIdx.x, lane = tid & 31, wid = tid >> 5;   // wid 0..15
    int g = lane >> 2, tig = lane & 3;
    int wm = wid & 3, wn = wid >> 2;                          // 32 rows x 32 cols
    int ob = blockIdx.x, tb = blockIdx.y;

    float acc[2][4][4];
#pragma unroll
    for (int mt = 0; mt < 2; ++mt)
#pragma unroll
        for (int nt = 0; nt < 4; ++nt)
#pragma unroll
            for (int q = 0; q < 4; ++q) acc[mt][nt][q] = 0.0f;

    const int srow = tid >> 2, sq = tid & 3;    // 128 rows x 4 quarters (8 pairs)
    const size_t arow0 = ((size_t)tb * 128 + srow) * 128 + sq * 8;
    const size_t wrow0 = (size_t)(ob * 128 + srow) * WPAIR + sq * 8;

    const uint32_t aOff = (uint32_t)((wm * 32 + ((lane & 8) ? 8 : 0) + (lane & 7)) * 36) * 4
                        + ((lane & 16) ? 16 : 0);
    const uint32_t bOff = (uint32_t)((wn * 32 + ((lane >> 4) << 3) + (lane & 7)) * 36) * 4
                        + ((lane & 8) << 1);

    auto stage = [&](int c, int s) {
        if (c < 8) {
            const unsigned* pa = (c < 4) ? &g_mp[arow0 + c * 32]
                                         : &g_xp[arow0 + (c - 4) * 32];
            const unsigned* pw = &g_Wp[wrow0 + c * 32];
            uint32_t d0 = sb + (uint32_t)(s * G2_STG + srow * 36 + sq * 8) * 4;
#pragma unroll
            for (int q = 0; q < 2; ++q) {
                cp16(d0 + q * 16,             pa + q * 4);
                cp16(d0 + G2_AS * 4 + q * 16, pw + q * 4);
            }
        }
        cp_commit();
    };

    stage(0, 0);
    stage(1, 1);
    int p = 0;
    for (int c = 0; c < 8; ++c) {
        cp_wait1();
        __syncthreads();
        int s2 = p + 2; if (s2 >= 3) s2 -= 3;
        stage(c + 2, s2);

        uint32_t aBase = sb + (uint32_t)(p * G2_STG) * 4 + aOff;
        uint32_t bBase = sb + (uint32_t)(p * G2_STG + G2_AS) * 4 + bOff;

#pragma unroll
        for (int kk = 0; kk < 4; ++kk) {
            unsigned ah[2][4];
#pragma unroll
            for (int mt = 0; mt < 2; ++mt)
                ldsm4(ah[mt][0], ah[mt][1], ah[mt][2], ah[mt][3],
                      aBase + mt * (16 * 36 * 4) + kk * 32);
#pragma unroll
            for (int np = 0; np < 2; ++np) {
                unsigned rb[4];
                ldsm4(rb[0], rb[1], rb[2], rb[3], bBase + np * (16 * 36 * 4) + kk * 32);
                mma16816(acc[0][2 * np],     ah[0], rb[0], rb[1]);
                mma16816(acc[0][2 * np + 1], ah[0], rb[2], rb[3]);
                mma16816(acc[1][2 * np],     ah[1], rb[0], rb[1]);
                mma16816(acc[1][2 * np + 1], ah[1], rb[2], rb[3]);
            }
        }
        if (++p == 3) p = 0;
    }

    // epilogue: relu, write h and h_n
    const size_t HSIZE = (size_t)BATCH * T * HID;
#pragma unroll
    for (int mt = 0; mt < 2; ++mt) {
        size_t row0 = (size_t)tb * 128 + wm * 32 + mt * 16 + g;
#pragma unroll
        for (int nt = 0; nt < 4; ++nt) {
            int col = ob * 128 + wn * 32 + nt * 8 + tig * 2;
            float2 v0 = make_float2(fmaxf(acc[mt][nt][0], 0.f), fmaxf(acc[mt][nt][1], 0.f));
            float2 v1 = make_float2(fmaxf(acc[mt][nt][2], 0.f), fmaxf(acc[mt][nt][3], 0.f));
            *(float2*)&out[row0 * HID + col] = v0;
            *(float2*)&out[(row0 + 8) * HID + col] = v1;
            if ((row0 & (size_t)(T - 1)) == (size_t)(T - 1))
                *(float2*)&out[HSIZE + (row0 >> 12) * HID + col] = v0;
            if (((row0 + 8) & (size_t)(T - 1)) == (size_t)(T - 1))
                *(float2*)&out[HSIZE + ((row0 + 8) >> 12) * HID + col] = v1;
        }
    }
}

// ---------------------------------------------------------------------------
extern "C" void kernel_launch(void* const* d_in, const int* in_sizes, int n_in,
                              void* d_out, int out_size) {
    const float* x  = (const float*)d_in[0];   // (32, 4096, 256)
    const float* Wu = (const float*)d_in[1];   // (1, 256)
    const float* Wh = (const float*)d_in[2];   // (512, 512)
    const float* H  = (const float*)d_in[3];   // (256, 4096)
    float* out = (float*)d_out;

    (void)in_sizes; (void)n_in; (void)out_size;

    static int smem_set = 0;
    if (!smem_set) {
        cudaFuncSetAttribute(k_conv_hmma, cudaFuncAttributeMaxDynamicSharedMemorySize,
                             CV_SMEM_BYTES);
        cudaFuncSetAttribute(k_gemm2_hmma, cudaFuncAttributeMaxDynamicSharedMemorySize,
                             G2_SMEM_BYTES);
        smem_set = 1;
    }

    k_front<<<UX_BLOCKS + PREP_BLOCKS, 256>>>(x, Wu, Wh, H);
    k_pack_u<<<(BATCH * USTRIDE + 255) / 256, 256>>>();
    k_conv_hmma<<<dim3(NB, 2, BATCH), 512, CV_SMEM_BYTES>>>();
    k_gemm2_hmma<<<dim3(HID / 128, BATCH * T / 128), 512, G2_SMEM_BYTES>>>(out);
}